// round 10
// baseline (speedup 1.0000x reference)
#include <cuda_runtime.h>
#include <cuda_fp16.h>

// ContinuousEmbedding via trig factorization + fp16 tables + half2 combine.
//   w_j = 0.5 + 0.5*cos(a)cos(j*pi/4) + 0.5*sin(a)sin(j*pi/4), a=(pi/4)(t+3)
//   out[x] = c0*A0[pbi] + c1*A1[pbi] + c2*A2[pbi]
//
// R9: halve shared-pipe INSTRUCTION count per x (theory: bound by LDS/STG
// instruction rate ~4cyc/op, not bytes). Each lane covers 8 dims; 16 lanes
// per x; warp does 2 x per iteration:
//   per 2x: 1 stage LDS.128 + 3 row LDS.128 + 2 STG.128  (was 10 ops per 2x)

#define NUM_POINTS 64
#define OUT_DIMS   128
#define V4_PER_ROW (OUT_DIMS / 4)     // 32
#define NPBI       64                 // pbi = pb+3 in [0,63] (pb in [-3,60])
#define ROW_BYTES  256                // 128 dims * 2B fp16
#define PBI_STRIDE 768                // 3 tables * 256B
#define TBL_BYTES  (NPBI * PBI_STRIDE)        // 49,152
#define WARPS_PB   16                 // 512 threads
#define STAGE_BYTES (WARPS_PB * 32 * 16)      // 8,192
#define SMEM_BYTES (TBL_BYTES + STAGE_BYTES)  // 57,344
#define RSQ2       0.70710678118654752440f
#define BLOCK      512

extern __shared__ unsigned char s_raw[];

__device__ __forceinline__ __half2 u2h(unsigned int u) {
    return *reinterpret_cast<const __half2*>(&u);
}

// Process one x-half: lane covers dims [8*sub, 8*sub+8) of x (base+xsel).
__device__ __forceinline__ void ce_body2(const float4 c,
                                         const unsigned char* __restrict__ s_base,
                                         int sub, float4* __restrict__ dst)
{
    const __half2 C0 = u2h(__float_as_uint(c.x));
    const __half2 C1 = u2h(__float_as_uint(c.y));
    const __half2 C2 = u2h(__float_as_uint(c.z));

    const unsigned char* row = s_base + __float_as_int(c.w) + sub * 16;
    const uint4 q0 = *reinterpret_cast<const uint4*>(row);                  // A0: 8 halves
    const uint4 q1 = *reinterpret_cast<const uint4*>(row + ROW_BYTES);      // A1
    const uint4 q2 = *reinterpret_cast<const uint4*>(row + 2 * ROW_BYTES);  // A2

    const __half2 r0 = __hfma2(u2h(q2.x), C2, __hfma2(u2h(q1.x), C1, __hmul2(u2h(q0.x), C0)));
    const __half2 r1 = __hfma2(u2h(q2.y), C2, __hfma2(u2h(q1.y), C1, __hmul2(u2h(q0.y), C0)));
    const __half2 r2 = __hfma2(u2h(q2.z), C2, __hfma2(u2h(q1.z), C1, __hmul2(u2h(q0.z), C0)));
    const __half2 r3 = __hfma2(u2h(q2.w), C2, __hfma2(u2h(q1.w), C1, __hmul2(u2h(q0.w), C0)));

    const float2 f0 = __half22float2(r0);
    const float2 f1 = __half22float2(r1);
    const float2 f2 = __half22float2(r2);
    const float2 f3 = __half22float2(r3);

    float4 oa, ob;
    oa.x = f0.x; oa.y = f0.y; oa.z = f1.x; oa.w = f1.y;
    ob.x = f2.x; ob.y = f2.y; ob.z = f3.x; ob.w = f3.y;
    __stcs(dst,     oa);
    __stcs(dst + 1, ob);
}

__global__ __launch_bounds__(BLOCK, 3)
void ContinuousEmbedding_89412629168402_kernel(const float* __restrict__ x,
                                               const float* __restrict__ emb,
                                               float* __restrict__ out,
                                               int n_x)
{
    // ---- build fp16 A0/A1/A2 tables (once per block) ----
    const float4* __restrict__ emb4 = reinterpret_cast<const float4*>(emb);
    {
        const float cj[8] = {1.f,  RSQ2, 0.f, -RSQ2, -1.f, -RSQ2,  0.f,  RSQ2};
        const float sj[8] = {0.f,  RSQ2, 1.f,  RSQ2,  0.f, -RSQ2, -1.f, -RSQ2};
        for (int tr = threadIdx.x; tr < NPBI * V4_PER_ROW; tr += BLOCK) {
            const int pbi = tr >> 5;
            const int ch  = tr & 31;
            const int pb  = pbi - 3;
            float4 a0 = make_float4(0.f,0.f,0.f,0.f);
            float4 a1 = a0, a2 = a0;
            #pragma unroll
            for (int j = 0; j < 8; ++j) {
                const int p = pb + j;
                if (p >= 0 && p < NUM_POINTS) {
                    const float4 e = __ldg(&emb4[p * V4_PER_ROW + ch]);
                    a0.x += e.x; a0.y += e.y; a0.z += e.z; a0.w += e.w;
                    a1.x = fmaf(cj[j], e.x, a1.x); a1.y = fmaf(cj[j], e.y, a1.y);
                    a1.z = fmaf(cj[j], e.z, a1.z); a1.w = fmaf(cj[j], e.w, a1.w);
                    a2.x = fmaf(sj[j], e.x, a2.x); a2.y = fmaf(sj[j], e.y, a2.y);
                    a2.z = fmaf(sj[j], e.z, a2.z); a2.w = fmaf(sj[j], e.w, a2.w);
                }
            }
            unsigned char* base = s_raw + pbi * PBI_STRIDE + ch * 8;
            __half2* d0 = reinterpret_cast<__half2*>(base);
            __half2* d1 = reinterpret_cast<__half2*>(base + ROW_BYTES);
            __half2* d2 = reinterpret_cast<__half2*>(base + 2 * ROW_BYTES);
            d0[0] = __floats2half2_rn(a0.x, a0.y);
            d0[1] = __floats2half2_rn(a0.z, a0.w);
            d1[0] = __floats2half2_rn(a1.x, a1.y);
            d1[1] = __floats2half2_rn(a1.z, a1.w);
            d2[0] = __floats2half2_rn(a2.x, a2.y);
            d2[1] = __floats2half2_rn(a2.z, a2.w);
        }
    }
    __syncthreads();

    const int lane    = threadIdx.x & 31;
    const int sub     = lane & 15;        // dim-group within x (8 dims)
    const int halfsel = lane >> 4;        // which x of the pair
    const int wl      = threadIdx.x >> 5;
    const int wid_g   = blockIdx.x * WARPS_PB + wl;
    const int w_total = gridDim.x * WARPS_PB;
    const int n_tiles = (n_x + 31) >> 5;

    float4* stage = reinterpret_cast<float4*>(s_raw + TBL_BYTES) + wl * 32;
    float4* __restrict__ out4 = reinterpret_cast<float4*>(out);

    const float cj[8] = {1.f,  RSQ2, 0.f, -RSQ2, -1.f, -RSQ2,  0.f,  RSQ2};
    const float sj[8] = {0.f,  RSQ2, 1.f,  RSQ2,  0.f, -RSQ2, -1.f, -RSQ2};

    for (int wt = wid_g; wt < n_tiles; wt += w_total) {
        const int base = wt << 5;

        // ---- per-lane precompute for this lane's x ----
        const int xi = base + lane;
        const float xv = (xi < n_x) ? x[xi] : 0.f;
        const float xs = (xv + 1.0f) * 32.0f;
        const float f  = floorf(xs);
        const int   pb = (int)f - 3;
        const float t  = xs - f;
        const float a  = 0.78539816339744830962f * (t + 3.0f);
        const float ca = __cosf(a);
        const float sa = __sinf(a);

        float n0 = 0.f, n1 = 0.f, n2 = 0.f;
        #pragma unroll
        for (int j = 0; j < 8; ++j) {
            const int p = pb + j;
            if (p >= 0 && p < NUM_POINTS) { n0 += 1.f; n1 += cj[j]; n2 += sj[j]; }
        }
        const float s   = 0.5f * (n0 + ca * n1 + sa * n2);
        const float inv = (s > 0.f) ? (1.0f / s) : 0.f;
        int pbi = pb + 3;
        pbi = max(0, min(NPBI - 1, pbi));

        const __half2 h0  = __float2half2_rn(0.5f * inv);
        const __half2 h1  = __float2half2_rn(0.5f * ca * inv);
        const __half2 h2c = __float2half2_rn(0.5f * sa * inv);

        float4 cf;
        cf.x = __uint_as_float(*reinterpret_cast<const unsigned int*>(&h0));
        cf.y = __uint_as_float(*reinterpret_cast<const unsigned int*>(&h1));
        cf.z = __uint_as_float(*reinterpret_cast<const unsigned int*>(&h2c));
        cf.w = __int_as_float(pbi * PBI_STRIDE);

        __syncwarp();                 // previous tile's readers are done
        stage[lane] = cf;
        __syncwarp();                 // staging visible to all lanes

        const int cnt = min(32, n_x - base);

        if (cnt == 32) {
            // full tile: 2 x per iteration (lanes 0-15 -> x_a, 16-31 -> x_b)
            #pragma unroll 4
            for (int kk = 0; kk < 16; ++kk) {
                const int xsel = 2 * kk + halfsel;
                const float4 c = stage[xsel];           // LDS.128, 2 addrs/warp
                float4* dst = out4 + (size_t)(base + xsel) * V4_PER_ROW + 2 * sub;
                ce_body2(c, s_raw, sub, dst);
            }
        } else {
            for (int kk = 0; kk < 16; ++kk) {
                const int xsel = 2 * kk + halfsel;
                if (xsel >= cnt) break;
                const float4 c = stage[xsel];
                float4* dst = out4 + (size_t)(base + xsel) * V4_PER_ROW + 2 * sub;
                ce_body2(c, s_raw, sub, dst);
            }
        }
    }
}

extern "C" void kernel_launch(void* const* d_in, const int* in_sizes, int n_in,
                              void* d_out, int out_size)
{
    const float* x   = (const float*)d_in[0];   // [64, 8192] f32
    const float* emb = (const float*)d_in[1];   // [64, 128]  f32
    float* out = (float*)d_out;                 // [64, 8192, 128] f32

    const int n_x = in_sizes[0];                // 524288

    static bool attr_set = false;
    if (!attr_set) {
        cudaFuncSetAttribute(ContinuousEmbedding_89412629168402_kernel,
                             cudaFuncAttributeMaxDynamicSharedMemorySize,
                             SMEM_BYTES);
        attr_set = true;
    }

    // 3 CTAs/SM * ~152 SMs, grid-stride over 32-x tiles
    const int blocks = 456;
    ContinuousEmbedding_89412629168402_kernel<<<blocks, BLOCK, SMEM_BYTES>>>(
        x, emb, out, n_x);
}

// round 11
// speedup vs baseline: 1.3885x; 1.3885x over previous
#include <cuda_runtime.h>
#include <cuda_fp16.h>

// ContinuousEmbedding via trig factorization + fp16 tables + half2 combine:
//   w_j = 0.5 + 0.5*cos(a)cos(j*pi/4) + 0.5*sin(a)sin(j*pi/4), a=(pi/4)(t+3)
//   out[x] = c0*A0[pbi] + c1*A1[pbi] + c2*A2[pbi]
//
// R10: R7 body (verified best: 47.6us ncu) + PIPELINED dynamic tile queue:
// the next tile's ticket is fetched by lane 0 *before* processing the
// current tile, so the ~318-cyc global-atomic latency is hidden under
// ~700 cyc of tile work (R5's queue stalled on it head-of-chunk).
// Targets the per-CTA completion spread (spr_max 1.1-1.3x, B300 doc) +
// the static 2-vs-3-tile imbalance.

#define NUM_POINTS 64
#define OUT_DIMS   128
#define V4_PER_ROW (OUT_DIMS / 4)     // 32
#define NPBI       64                 // pbi = pb+3 in [0,63] (pb in [-3,60])
#define ROW_BYTES  256                // 128 dims * 2B fp16
#define PBI_STRIDE 768                // 3 tables * 256B
#define TBL_BYTES  (NPBI * PBI_STRIDE)        // 49,152
#define WARPS_PB   16                 // 512 threads
#define STAGE_BYTES (WARPS_PB * 32 * 16)      // 8,192
#define SMEM_BYTES (TBL_BYTES + STAGE_BYTES)  // 57,344
#define RSQ2       0.70710678118654752440f
#define BLOCK      512

__device__ unsigned int g_tile_ctr;

__global__ void ce_reset_ctr() { g_tile_ctr = 0u; }

extern __shared__ unsigned char s_raw[];

__global__ __launch_bounds__(BLOCK, 3)
void ContinuousEmbedding_89412629168402_kernel(const float* __restrict__ x,
                                               const float* __restrict__ emb,
                                               float* __restrict__ out,
                                               int n_x)
{
    // ---- build fp16 A0/A1/A2 tables (once per block) ----
    const float4* __restrict__ emb4 = reinterpret_cast<const float4*>(emb);
    {
        const float cj[8] = {1.f,  RSQ2, 0.f, -RSQ2, -1.f, -RSQ2,  0.f,  RSQ2};
        const float sj[8] = {0.f,  RSQ2, 1.f,  RSQ2,  0.f, -RSQ2, -1.f, -RSQ2};
        for (int tr = threadIdx.x; tr < NPBI * V4_PER_ROW; tr += BLOCK) {
            const int pbi = tr >> 5;
            const int ch  = tr & 31;
            const int pb  = pbi - 3;
            float4 a0 = make_float4(0.f,0.f,0.f,0.f);
            float4 a1 = a0, a2 = a0;
            #pragma unroll
            for (int j = 0; j < 8; ++j) {
                const int p = pb + j;
                if (p >= 0 && p < NUM_POINTS) {
                    const float4 e = __ldg(&emb4[p * V4_PER_ROW + ch]);
                    a0.x += e.x; a0.y += e.y; a0.z += e.z; a0.w += e.w;
                    a1.x = fmaf(cj[j], e.x, a1.x); a1.y = fmaf(cj[j], e.y, a1.y);
                    a1.z = fmaf(cj[j], e.z, a1.z); a1.w = fmaf(cj[j], e.w, a1.w);
                    a2.x = fmaf(sj[j], e.x, a2.x); a2.y = fmaf(sj[j], e.y, a2.y);
                    a2.z = fmaf(sj[j], e.z, a2.z); a2.w = fmaf(sj[j], e.w, a2.w);
                }
            }
            unsigned char* base = s_raw + pbi * PBI_STRIDE + ch * 8;
            __half2* d0 = reinterpret_cast<__half2*>(base);
            __half2* d1 = reinterpret_cast<__half2*>(base + ROW_BYTES);
            __half2* d2 = reinterpret_cast<__half2*>(base + 2 * ROW_BYTES);
            d0[0] = __floats2half2_rn(a0.x, a0.y);
            d0[1] = __floats2half2_rn(a0.z, a0.w);
            d1[0] = __floats2half2_rn(a1.x, a1.y);
            d1[1] = __floats2half2_rn(a1.z, a1.w);
            d2[0] = __floats2half2_rn(a2.x, a2.y);
            d2[1] = __floats2half2_rn(a2.z, a2.w);
        }
    }
    __syncthreads();

    const int lane = threadIdx.x & 31;
    const int wl   = threadIdx.x >> 5;
    const int n_tiles = (n_x + 31) >> 5;

    float4* stage = reinterpret_cast<float4*>(s_raw + TBL_BYTES) + wl * 32;
    float4* __restrict__ out4 = reinterpret_cast<float4*>(out);

    const float cj[8] = {1.f,  RSQ2, 0.f, -RSQ2, -1.f, -RSQ2,  0.f,  RSQ2};
    const float sj[8] = {0.f,  RSQ2, 1.f,  RSQ2,  0.f, -RSQ2, -1.f, -RSQ2};

    // ---- pipelined dynamic tile queue ----
    unsigned int next = 0;
    if (lane == 0) next = atomicAdd(&g_tile_ctr, 1u);
    next = __shfl_sync(0xffffffffu, next, 0);

    while (next < (unsigned int)n_tiles) {
        const int wt = (int)next;

        // prefetch the NEXT ticket; consumed after this tile's work
        unsigned int nxt_raw = 0;
        if (lane == 0) nxt_raw = atomicAdd(&g_tile_ctr, 1u);

        const int base = wt << 5;

        // ---- per-lane precompute for this lane's x ----
        const int xi = base + lane;
        const float xv = (xi < n_x) ? x[xi] : 0.f;
        const float xs = (xv + 1.0f) * 32.0f;
        const float f  = floorf(xs);
        const int   pb = (int)f - 3;
        const float t  = xs - f;
        const float a  = 0.78539816339744830962f * (t + 3.0f);
        const float ca = __cosf(a);
        const float sa = __sinf(a);

        float n0 = 0.f, n1 = 0.f, n2 = 0.f;
        #pragma unroll
        for (int j = 0; j < 8; ++j) {
            const int p = pb + j;
            if (p >= 0 && p < NUM_POINTS) { n0 += 1.f; n1 += cj[j]; n2 += sj[j]; }
        }
        const float s   = 0.5f * (n0 + ca * n1 + sa * n2);
        const float inv = (s > 0.f) ? (1.0f / s) : 0.f;
        int pbi = pb + 3;
        pbi = max(0, min(NPBI - 1, pbi));

        const __half2 h0  = __float2half2_rn(0.5f * inv);
        const __half2 h1  = __float2half2_rn(0.5f * ca * inv);
        const __half2 h2c = __float2half2_rn(0.5f * sa * inv);

        float4 cf;
        cf.x = __uint_as_float(*reinterpret_cast<const unsigned int*>(&h0));
        cf.y = __uint_as_float(*reinterpret_cast<const unsigned int*>(&h1));
        cf.z = __uint_as_float(*reinterpret_cast<const unsigned int*>(&h2c));
        cf.w = __int_as_float(pbi * PBI_STRIDE);

        __syncwarp();                 // previous tile's readers are done
        stage[lane] = cf;
        __syncwarp();                 // staging visible to all lanes

        // ---- broadcast loop: one x per k ----
        const int cnt = min(32, n_x - base);
        for (int k = 0; k < cnt; ++k) {
            const float4 c = stage[k];               // broadcast LDS.128
            const unsigned int b0 = __float_as_uint(c.x);
            const unsigned int b1 = __float_as_uint(c.y);
            const unsigned int b2 = __float_as_uint(c.z);
            const __half2 C0 = *reinterpret_cast<const __half2*>(&b0);
            const __half2 C1 = *reinterpret_cast<const __half2*>(&b1);
            const __half2 C2 = *reinterpret_cast<const __half2*>(&b2);

            const unsigned char* row = s_raw + __float_as_int(c.w) + lane * 8;
            const uint2 u0 = *reinterpret_cast<const uint2*>(row);
            const uint2 u1 = *reinterpret_cast<const uint2*>(row + ROW_BYTES);
            const uint2 u2 = *reinterpret_cast<const uint2*>(row + 2 * ROW_BYTES);

            const __half2 A0l = *reinterpret_cast<const __half2*>(&u0.x);
            const __half2 A0h = *reinterpret_cast<const __half2*>(&u0.y);
            const __half2 A1l = *reinterpret_cast<const __half2*>(&u1.x);
            const __half2 A1h = *reinterpret_cast<const __half2*>(&u1.y);
            const __half2 A2l = *reinterpret_cast<const __half2*>(&u2.x);
            const __half2 A2h = *reinterpret_cast<const __half2*>(&u2.y);

            const __half2 accl = __hfma2(A2l, C2, __hfma2(A1l, C1, __hmul2(A0l, C0)));
            const __half2 acch = __hfma2(A2h, C2, __hfma2(A1h, C1, __hmul2(A0h, C0)));

            const float2 lo = __half22float2(accl);
            const float2 hi = __half22float2(acch);
            float4 acc;
            acc.x = lo.x; acc.y = lo.y; acc.z = hi.x; acc.w = hi.y;

            __stcs(&out4[(size_t)(base + k) * V4_PER_ROW + lane], acc);
        }

        // consume the prefetched ticket (atomic latency hidden by tile work)
        next = __shfl_sync(0xffffffffu, nxt_raw, 0);
    }
}

extern "C" void kernel_launch(void* const* d_in, const int* in_sizes, int n_in,
                              void* d_out, int out_size)
{
    const float* x   = (const float*)d_in[0];   // [64, 8192] f32
    const float* emb = (const float*)d_in[1];   // [64, 128]  f32
    float* out = (float*)d_out;                 // [64, 8192, 128] f32

    const int n_x = in_sizes[0];                // 524288

    static bool attr_set = false;
    if (!attr_set) {
        cudaFuncSetAttribute(ContinuousEmbedding_89412629168402_kernel,
                             cudaFuncAttributeMaxDynamicSharedMemorySize,
                             SMEM_BYTES);
        attr_set = true;
    }

    ce_reset_ctr<<<1, 1>>>();
    // 3 CTAs/SM * ~152 SMs, persistent warps on a pipelined tile queue
    const int blocks = 456;
    ContinuousEmbedding_89412629168402_kernel<<<blocks, BLOCK, SMEM_BYTES>>>(
        x, emb, out, n_x);
}

// round 12
// speedup vs baseline: 1.4943x; 1.0762x over previous
#include <cuda_runtime.h>
#include <cuda_fp16.h>

// ContinuousEmbedding via trig factorization + fp16 tables + half2 combine:
//   w_j = 0.5 + 0.5*cos(a)cos(j*pi/4) + 0.5*sin(a)sin(j*pi/4), a=(pi/4)(t+3)
//   out[x] = c0*A0[pbi] + c1*A1[pbi] + c2*A2[pbi]
//
// R11: R9's 8-dims-per-lane layout (2 x per warp-iteration) but with a
// single 256-bit st.global.v8.f32 per lane -> the warp writes 1024
// CONTIGUOUS bytes per store instruction (fixes R9's broken coalescing).
// Tests whether the ~48us plateau is store-pipeline-bound (expect 42-45us)
// or raw DRAM-write-drain-bound (expect flat; then R7 is the floor).

#define NUM_POINTS 64
#define OUT_DIMS   128
#define V4_PER_ROW (OUT_DIMS / 4)     // 32
#define NPBI       64                 // pbi = pb+3 in [0,63] (pb in [-3,60])
#define ROW_BYTES  256                // 128 dims * 2B fp16
#define PBI_STRIDE 768                // 3 tables * 256B
#define TBL_BYTES  (NPBI * PBI_STRIDE)        // 49,152
#define WARPS_PB   16                 // 512 threads
#define STAGE_BYTES (WARPS_PB * 32 * 16)      // 8,192
#define SMEM_BYTES (TBL_BYTES + STAGE_BYTES)  // 57,344
#define RSQ2       0.70710678118654752440f
#define BLOCK      512

extern __shared__ unsigned char s_raw[];

__device__ __forceinline__ __half2 u2h(unsigned int u) {
    return *reinterpret_cast<const __half2*>(&u);
}

__device__ __forceinline__ void stg256(float* __restrict__ p,
                                       float f0, float f1, float f2, float f3,
                                       float f4, float f5, float f6, float f7)
{
    asm volatile("st.global.cs.v8.f32 [%0], {%1,%2,%3,%4,%5,%6,%7,%8};"
                 :: "l"(p), "f"(f0), "f"(f1), "f"(f2), "f"(f3),
                    "f"(f4), "f"(f5), "f"(f6), "f"(f7)
                 : "memory");
}

__global__ __launch_bounds__(BLOCK, 3)
void ContinuousEmbedding_89412629168402_kernel(const float* __restrict__ x,
                                               const float* __restrict__ emb,
                                               float* __restrict__ out,
                                               int n_x)
{
    // ---- build fp16 A0/A1/A2 tables (once per block) ----
    const float4* __restrict__ emb4 = reinterpret_cast<const float4*>(emb);
    {
        const float cj[8] = {1.f,  RSQ2, 0.f, -RSQ2, -1.f, -RSQ2,  0.f,  RSQ2};
        const float sj[8] = {0.f,  RSQ2, 1.f,  RSQ2,  0.f, -RSQ2, -1.f, -RSQ2};
        for (int tr = threadIdx.x; tr < NPBI * V4_PER_ROW; tr += BLOCK) {
            const int pbi = tr >> 5;
            const int ch  = tr & 31;
            const int pb  = pbi - 3;
            float4 a0 = make_float4(0.f,0.f,0.f,0.f);
            float4 a1 = a0, a2 = a0;
            #pragma unroll
            for (int j = 0; j < 8; ++j) {
                const int p = pb + j;
                if (p >= 0 && p < NUM_POINTS) {
                    const float4 e = __ldg(&emb4[p * V4_PER_ROW + ch]);
                    a0.x += e.x; a0.y += e.y; a0.z += e.z; a0.w += e.w;
                    a1.x = fmaf(cj[j], e.x, a1.x); a1.y = fmaf(cj[j], e.y, a1.y);
                    a1.z = fmaf(cj[j], e.z, a1.z); a1.w = fmaf(cj[j], e.w, a1.w);
                    a2.x = fmaf(sj[j], e.x, a2.x); a2.y = fmaf(sj[j], e.y, a2.y);
                    a2.z = fmaf(sj[j], e.z, a2.z); a2.w = fmaf(sj[j], e.w, a2.w);
                }
            }
            unsigned char* base = s_raw + pbi * PBI_STRIDE + ch * 8;
            __half2* d0 = reinterpret_cast<__half2*>(base);
            __half2* d1 = reinterpret_cast<__half2*>(base + ROW_BYTES);
            __half2* d2 = reinterpret_cast<__half2*>(base + 2 * ROW_BYTES);
            d0[0] = __floats2half2_rn(a0.x, a0.y);
            d0[1] = __floats2half2_rn(a0.z, a0.w);
            d1[0] = __floats2half2_rn(a1.x, a1.y);
            d1[1] = __floats2half2_rn(a1.z, a1.w);
            d2[0] = __floats2half2_rn(a2.x, a2.y);
            d2[1] = __floats2half2_rn(a2.z, a2.w);
        }
    }
    __syncthreads();

    const int lane    = threadIdx.x & 31;
    const int sub     = lane & 15;        // dim-group (8 dims) within x
    const int halfsel = lane >> 4;        // which x of the pair
    const int wl      = threadIdx.x >> 5;
    const int wid_g   = blockIdx.x * WARPS_PB + wl;
    const int w_total = gridDim.x * WARPS_PB;
    const int n_tiles = (n_x + 31) >> 5;

    float4* stage = reinterpret_cast<float4*>(s_raw + TBL_BYTES) + wl * 32;

    const float cj[8] = {1.f,  RSQ2, 0.f, -RSQ2, -1.f, -RSQ2,  0.f,  RSQ2};
    const float sj[8] = {0.f,  RSQ2, 1.f,  RSQ2,  0.f, -RSQ2, -1.f, -RSQ2};

    for (int wt = wid_g; wt < n_tiles; wt += w_total) {
        const int base = wt << 5;

        // ---- per-lane precompute for this lane's x ----
        const int xi = base + lane;
        const float xv = (xi < n_x) ? x[xi] : 0.f;
        const float xs = (xv + 1.0f) * 32.0f;
        const float f  = floorf(xs);
        const int   pb = (int)f - 3;
        const float t  = xs - f;
        const float a  = 0.78539816339744830962f * (t + 3.0f);
        const float ca = __cosf(a);
        const float sa = __sinf(a);

        float n0 = 0.f, n1 = 0.f, n2 = 0.f;
        #pragma unroll
        for (int j = 0; j < 8; ++j) {
            const int p = pb + j;
            if (p >= 0 && p < NUM_POINTS) { n0 += 1.f; n1 += cj[j]; n2 += sj[j]; }
        }
        const float s   = 0.5f * (n0 + ca * n1 + sa * n2);
        const float inv = (s > 0.f) ? (1.0f / s) : 0.f;
        int pbi = pb + 3;
        pbi = max(0, min(NPBI - 1, pbi));

        const __half2 h0  = __float2half2_rn(0.5f * inv);
        const __half2 h1  = __float2half2_rn(0.5f * ca * inv);
        const __half2 h2c = __float2half2_rn(0.5f * sa * inv);

        float4 cf;
        cf.x = __uint_as_float(*reinterpret_cast<const unsigned int*>(&h0));
        cf.y = __uint_as_float(*reinterpret_cast<const unsigned int*>(&h1));
        cf.z = __uint_as_float(*reinterpret_cast<const unsigned int*>(&h2c));
        cf.w = __int_as_float(pbi * PBI_STRIDE);

        __syncwarp();                 // previous tile's readers are done
        stage[lane] = cf;
        __syncwarp();                 // staging visible to all lanes

        const int cnt = min(32, n_x - base);

        // 2 x per iteration: lanes 0-15 -> x(2kk), lanes 16-31 -> x(2kk+1).
        // One STG.256 per lane: warp writes 1024 contiguous bytes.
        #pragma unroll 4
        for (int kk = 0; kk < 16; ++kk) {
            const int xsel = 2 * kk + halfsel;
            if (xsel >= cnt) break;

            const float4 c = stage[xsel];
            const __half2 C0 = u2h(__float_as_uint(c.x));
            const __half2 C1 = u2h(__float_as_uint(c.y));
            const __half2 C2 = u2h(__float_as_uint(c.z));

            const unsigned char* row = s_raw + __float_as_int(c.w) + sub * 16;
            const uint4 q0 = *reinterpret_cast<const uint4*>(row);
            const uint4 q1 = *reinterpret_cast<const uint4*>(row + ROW_BYTES);
            const uint4 q2 = *reinterpret_cast<const uint4*>(row + 2 * ROW_BYTES);

            const __half2 r0 = __hfma2(u2h(q2.x), C2, __hfma2(u2h(q1.x), C1, __hmul2(u2h(q0.x), C0)));
            const __half2 r1 = __hfma2(u2h(q2.y), C2, __hfma2(u2h(q1.y), C1, __hmul2(u2h(q0.y), C0)));
            const __half2 r2 = __hfma2(u2h(q2.z), C2, __hfma2(u2h(q1.z), C1, __hmul2(u2h(q0.z), C0)));
            const __half2 r3 = __hfma2(u2h(q2.w), C2, __hfma2(u2h(q1.w), C1, __hmul2(u2h(q0.w), C0)));

            const float2 f0 = __half22float2(r0);
            const float2 f1 = __half22float2(r1);
            const float2 f2 = __half22float2(r2);
            const float2 f3 = __half22float2(r3);

            float* dst = out + (size_t)(base + xsel) * OUT_DIMS + sub * 8;
            stg256(dst, f0.x, f0.y, f1.x, f1.y, f2.x, f2.y, f3.x, f3.y);
        }
    }
}

extern "C" void kernel_launch(void* const* d_in, const int* in_sizes, int n_in,
                              void* d_out, int out_size)
{
    const float* x   = (const float*)d_in[0];   // [64, 8192] f32
    const float* emb = (const float*)d_in[1];   // [64, 128]  f32
    float* out = (float*)d_out;                 // [64, 8192, 128] f32

    const int n_x = in_sizes[0];                // 524288

    static bool attr_set = false;
    if (!attr_set) {
        cudaFuncSetAttribute(ContinuousEmbedding_89412629168402_kernel,
                             cudaFuncAttributeMaxDynamicSharedMemorySize,
                             SMEM_BYTES);
        attr_set = true;
    }

    // 3 CTAs/SM * ~152 SMs, grid-stride over 32-x tiles
    const int blocks = 456;
    ContinuousEmbedding_89412629168402_kernel<<<blocks, BLOCK, SMEM_BYTES>>>(
        x, emb, out, n_x);
}

// round 13
// speedup vs baseline: 1.6050x; 1.0741x over previous
#include <cuda_runtime.h>
#include <cuda_fp16.h>

// ContinuousEmbedding via trig factorization + fp16 tables + half2 combine:
//   w_j = 0.5 + 0.5*cos(a)cos(j*pi/4) + 0.5*sin(a)sin(j*pi/4), a=(pi/4)(t+3)
//   out[x] = c0*A0[pbi] + c1*A1[pbi] + c2*A2[pbi]
//
// R12: kernel body = R7 (verified best; at the DRAM write-drain floor).
// Change: A0/A1/A2 fp16 tables are built ONCE by a small builder kernel
// into a __device__ global, and each main block just block-copies 48KB
// gmem(L2)->smem, replacing the per-block rebuild (32 masked LDG + ~100
// FLOP + 12 cvt per thread) with 6 LDG.128 + 6 STS.128 per thread.

#define NUM_POINTS 64
#define OUT_DIMS   128
#define V4_PER_ROW (OUT_DIMS / 4)     // 32
#define NPBI       64                 // pbi = pb+3 in [0,63] (pb in [-3,60])
#define ROW_BYTES  256                // 128 dims * 2B fp16
#define PBI_STRIDE 768                // 3 tables * 256B
#define TBL_BYTES  (NPBI * PBI_STRIDE)        // 49,152
#define TBL_U4     (TBL_BYTES / 16)           // 3,072 uint4
#define WARPS_PB   16                 // 512 threads
#define STAGE_BYTES (WARPS_PB * 32 * 16)      // 8,192
#define SMEM_BYTES (TBL_BYTES + STAGE_BYTES)  // 57,344
#define RSQ2       0.70710678118654752440f
#define BLOCK      512

__device__ __align__(16) unsigned char g_tbl[TBL_BYTES];

extern __shared__ unsigned char s_raw[];

// ---- builder: one block per pbi, one thread per 4-dim chunk ----
__global__ void ce_build_tbl(const float* __restrict__ emb)
{
    const float cj[8] = {1.f,  RSQ2, 0.f, -RSQ2, -1.f, -RSQ2,  0.f,  RSQ2};
    const float sj[8] = {0.f,  RSQ2, 1.f,  RSQ2,  0.f, -RSQ2, -1.f, -RSQ2};

    const int pbi = blockIdx.x;        // 0..63
    const int ch  = threadIdx.x;       // 0..31
    const int pb  = pbi - 3;

    const float4* __restrict__ emb4 = reinterpret_cast<const float4*>(emb);

    float4 a0 = make_float4(0.f,0.f,0.f,0.f);
    float4 a1 = a0, a2 = a0;
    #pragma unroll
    for (int j = 0; j < 8; ++j) {
        const int p = pb + j;
        if (p >= 0 && p < NUM_POINTS) {
            const float4 e = __ldg(&emb4[p * V4_PER_ROW + ch]);
            a0.x += e.x; a0.y += e.y; a0.z += e.z; a0.w += e.w;
            a1.x = fmaf(cj[j], e.x, a1.x); a1.y = fmaf(cj[j], e.y, a1.y);
            a1.z = fmaf(cj[j], e.z, a1.z); a1.w = fmaf(cj[j], e.w, a1.w);
            a2.x = fmaf(sj[j], e.x, a2.x); a2.y = fmaf(sj[j], e.y, a2.y);
            a2.z = fmaf(sj[j], e.z, a2.z); a2.w = fmaf(sj[j], e.w, a2.w);
        }
    }
    unsigned char* base = g_tbl + pbi * PBI_STRIDE + ch * 8;
    __half2* d0 = reinterpret_cast<__half2*>(base);
    __half2* d1 = reinterpret_cast<__half2*>(base + ROW_BYTES);
    __half2* d2 = reinterpret_cast<__half2*>(base + 2 * ROW_BYTES);
    d0[0] = __floats2half2_rn(a0.x, a0.y);
    d0[1] = __floats2half2_rn(a0.z, a0.w);
    d1[0] = __floats2half2_rn(a1.x, a1.y);
    d1[1] = __floats2half2_rn(a1.z, a1.w);
    d2[0] = __floats2half2_rn(a2.x, a2.y);
    d2[1] = __floats2half2_rn(a2.z, a2.w);
}

__global__ __launch_bounds__(BLOCK, 3)
void ContinuousEmbedding_89412629168402_kernel(const float* __restrict__ x,
                                               float* __restrict__ out,
                                               int n_x)
{
    // ---- prologue: straight copy of the prebuilt table into smem ----
    {
        const uint4* __restrict__ src = reinterpret_cast<const uint4*>(g_tbl);
        uint4* dst = reinterpret_cast<uint4*>(s_raw);
        #pragma unroll
        for (int i = threadIdx.x; i < TBL_U4; i += BLOCK)
            dst[i] = __ldg(&src[i]);
    }
    __syncthreads();

    const int lane    = threadIdx.x & 31;
    const int wl      = threadIdx.x >> 5;
    const int wid_g   = blockIdx.x * WARPS_PB + wl;
    const int w_total = gridDim.x * WARPS_PB;
    const int n_tiles = (n_x + 31) >> 5;

    float4* stage = reinterpret_cast<float4*>(s_raw + TBL_BYTES) + wl * 32;
    float4* __restrict__ out4 = reinterpret_cast<float4*>(out);

    const float cj[8] = {1.f,  RSQ2, 0.f, -RSQ2, -1.f, -RSQ2,  0.f,  RSQ2};
    const float sj[8] = {0.f,  RSQ2, 1.f,  RSQ2,  0.f, -RSQ2, -1.f, -RSQ2};

    for (int wt = wid_g; wt < n_tiles; wt += w_total) {
        const int base = wt << 5;

        // ---- per-lane precompute for this lane's x ----
        const int xi = base + lane;
        const float xv = (xi < n_x) ? x[xi] : 0.f;
        const float xs = (xv + 1.0f) * 32.0f;
        const float f  = floorf(xs);
        const int   pb = (int)f - 3;
        const float t  = xs - f;
        const float a  = 0.78539816339744830962f * (t + 3.0f);
        const float ca = __cosf(a);
        const float sa = __sinf(a);

        float n0 = 0.f, n1 = 0.f, n2 = 0.f;
        #pragma unroll
        for (int j = 0; j < 8; ++j) {
            const int p = pb + j;
            if (p >= 0 && p < NUM_POINTS) { n0 += 1.f; n1 += cj[j]; n2 += sj[j]; }
        }
        const float s   = 0.5f * (n0 + ca * n1 + sa * n2);
        const float inv = (s > 0.f) ? (1.0f / s) : 0.f;
        int pbi = pb + 3;
        pbi = max(0, min(NPBI - 1, pbi));

        const __half2 h0  = __float2half2_rn(0.5f * inv);
        const __half2 h1  = __float2half2_rn(0.5f * ca * inv);
        const __half2 h2c = __float2half2_rn(0.5f * sa * inv);

        float4 cf;
        cf.x = __uint_as_float(*reinterpret_cast<const unsigned int*>(&h0));
        cf.y = __uint_as_float(*reinterpret_cast<const unsigned int*>(&h1));
        cf.z = __uint_as_float(*reinterpret_cast<const unsigned int*>(&h2c));
        cf.w = __int_as_float(pbi * PBI_STRIDE);

        __syncwarp();                 // previous tile's readers are done
        stage[lane] = cf;
        __syncwarp();                 // staging visible to all lanes

        // ---- broadcast loop: one x per k ----
        const int cnt = min(32, n_x - base);
        for (int k = 0; k < cnt; ++k) {
            const float4 c = stage[k];               // broadcast LDS.128
            const unsigned int b0 = __float_as_uint(c.x);
            const unsigned int b1 = __float_as_uint(c.y);
            const unsigned int b2 = __float_as_uint(c.z);
            const __half2 C0 = *reinterpret_cast<const __half2*>(&b0);
            const __half2 C1 = *reinterpret_cast<const __half2*>(&b1);
            const __half2 C2 = *reinterpret_cast<const __half2*>(&b2);

            const unsigned char* row = s_raw + __float_as_int(c.w) + lane * 8;
            const uint2 u0 = *reinterpret_cast<const uint2*>(row);
            const uint2 u1 = *reinterpret_cast<const uint2*>(row + ROW_BYTES);
            const uint2 u2 = *reinterpret_cast<const uint2*>(row + 2 * ROW_BYTES);

            const __half2 A0l = *reinterpret_cast<const __half2*>(&u0.x);
            const __half2 A0h = *reinterpret_cast<const __half2*>(&u0.y);
            const __half2 A1l = *reinterpret_cast<const __half2*>(&u1.x);
            const __half2 A1h = *reinterpret_cast<const __half2*>(&u1.y);
            const __half2 A2l = *reinterpret_cast<const __half2*>(&u2.x);
            const __half2 A2h = *reinterpret_cast<const __half2*>(&u2.y);

            const __half2 accl = __hfma2(A2l, C2, __hfma2(A1l, C1, __hmul2(A0l, C0)));
            const __half2 acch = __hfma2(A2h, C2, __hfma2(A1h, C1, __hmul2(A0h, C0)));

            const float2 lo = __half22float2(accl);
            const float2 hi = __half22float2(acch);
            float4 acc;
            acc.x = lo.x; acc.y = lo.y; acc.z = hi.x; acc.w = hi.y;

            __stcs(&out4[(size_t)(base + k) * V4_PER_ROW + lane], acc);
        }
    }
}

extern "C" void kernel_launch(void* const* d_in, const int* in_sizes, int n_in,
                              void* d_out, int out_size)
{
    const float* x   = (const float*)d_in[0];   // [64, 8192] f32
    const float* emb = (const float*)d_in[1];   // [64, 128]  f32
    float* out = (float*)d_out;                 // [64, 8192, 128] f32

    const int n_x = in_sizes[0];                // 524288

    static bool attr_set = false;
    if (!attr_set) {
        cudaFuncSetAttribute(ContinuousEmbedding_89412629168402_kernel,
                             cudaFuncAttributeMaxDynamicSharedMemorySize,
                             SMEM_BYTES);
        attr_set = true;
    }

    // 1) build the 48KB fp16 table once (64 blocks x 32 threads)
    ce_build_tbl<<<NPBI, 32>>>(emb);
    // 2) main kernel: 3 CTAs/SM * ~152 SMs, grid-stride over 32-x tiles
    const int blocks = 456;
    ContinuousEmbedding_89412629168402_kernel<<<blocks, BLOCK, SMEM_BYTES>>>(
        x, out, n_x);
}